// round 15
// baseline (speedup 1.0000x reference)
#include <cuda_runtime.h>
#include <cstdint>

// MXFP8 E4M3 quantize->dequantize, 32-element blocks along last axis.
// R14 = R13 resubmitted unchanged (R13 hit a GB300 container/broker infra
// failure, no measurement). Zero-shuffle variant: each thread owns ONE full
// MX block (32 contiguous floats) via 4x front-batched LDG.E.256 (32 lines
// in flight per warp, 4KiB contiguous per warp per batch). Block amax is
// purely thread-local: no shfl, no cross-lane dependency between load and
// quantize. __launch_bounds__(256,6) caps regs at 42 (1536 thr/SM, 75%
// theoretical occ). Tests whether doubled per-warp MLP + removed SHFL
// serialization beats the residency loss.
//
// All scales are exact powers of two built by bit manipulation, so every
// multiply matches the reference's fp32 divide bit-for-bit.

static constexpr int EMAX = 8;           // e4m3
static constexpr float MAX_NORM = 448.0f;

__device__ __forceinline__ void ldg256cs(const float* p, float* v) {
    asm volatile(
        "ld.global.cs.v8.f32 {%0,%1,%2,%3,%4,%5,%6,%7}, [%8];"
        : "=f"(v[0]), "=f"(v[1]), "=f"(v[2]), "=f"(v[3]),
          "=f"(v[4]), "=f"(v[5]), "=f"(v[6]), "=f"(v[7])
        : "l"(p));
}

__device__ __forceinline__ void stg256cs(float* p, const float* v) {
    asm volatile(
        "st.global.cs.v8.f32 [%0], {%1,%2,%3,%4,%5,%6,%7,%8};"
        :: "l"(p),
           "f"(v[0]), "f"(v[1]), "f"(v[2]), "f"(v[3]),
           "f"(v[4]), "f"(v[5]), "f"(v[6]), "f"(v[7])
        : "memory");
}

__device__ __forceinline__ float quant_e4m3(float x, float iscale, float scale) {
    float a = x * iscale;                          // exact (iscale = 2^k)
    uint32_t au = __float_as_uint(a);
    uint32_t ab = au & 0x7fffffffu;                // |a|
    int pe = (int)(ab >> 23) - 127;                // floor(log2|a|), exact for normals
    pe = max(pe, -6);                              // MIN_EXP (denorm region clamp)
    // lshift = 2^(3-pe), inv_lshift = 2^(pe-3); pe in [-6, 8] -> both normal
    float lsh  = __uint_as_float((uint32_t)(130 - pe) << 23);
    float ilsh = __uint_as_float((uint32_t)(124 + pe) << 23);
    // round-half-away-from-zero on magnitude: product is exact, +0.5 rounds once
    float r = floorf(__uint_as_float(ab) * lsh + 0.5f);
    float m = fminf(r * ilsh, MAX_NORM);           // saturate to e4m3 max normal
    float res = m * scale;
    return __uint_as_float(__float_as_uint(res) | (au & 0x80000000u));
}

__global__ void __launch_bounds__(256, 6) mxq_kernel(const float* __restrict__ in,
                                                     float* __restrict__ out) {
    int gid = blockIdx.x * blockDim.x + threadIdx.x;
    long base = (long)gid * 32;                    // one full MX block

    // Front-batched 256-bit loads: 4 per thread, 32 lines in flight per warp
    float v[4][8];
    ldg256cs(in + base,      v[0]);
    ldg256cs(in + base + 8,  v[1]);
    ldg256cs(in + base + 16, v[2]);
    ldg256cs(in + base + 24, v[3]);

    // Thread-local amax over all 32 — no shuffles, no cross-lane dependency
    float m = 0.0f;
#pragma unroll
    for (int g = 0; g < 4; g++)
#pragma unroll
        for (int i = 0; i < 8; i++)
            m = fmaxf(m, fabsf(v[g][i]));

    int e = (int)(__float_as_uint(m) >> 23);       // m >= 0, no sign bit
    int se = e - 127 - EMAX;
    se = max(se, -127);
    float scale  = __uint_as_float((uint32_t)(se + 127) << 23);
    float iscale = __uint_as_float((uint32_t)(127 - se) << 23);

    // Quantize + store each 8-group in turn so registers retire progressively
#pragma unroll
    for (int g = 0; g < 4; g++) {
#pragma unroll
        for (int i = 0; i < 8; i++)
            v[g][i] = quant_e4m3(v[g][i], iscale, scale);
        stg256cs(out + base + g * 8, v[g]);
    }
}

extern "C" void kernel_launch(void* const* d_in, const int* in_sizes, int n_in,
                              void* d_out, int out_size) {
    const float* in = (const float*)d_in[0];
    float* out = (float*)d_out;
    int n = out_size;                              // 67,108,864 floats
    int threads = 256;
    int total_threads = n / 32;                    // 2,097,152 (one MX block each)
    int blocks = total_threads / threads;          // 8192
    mxq_kernel<<<blocks, threads>>>(in, out);
}

// round 16
// speedup vs baseline: 1.2538x; 1.2538x over previous
#include <cuda_runtime.h>
#include <cstdint>

// MXFP8 E4M3 quantize->dequantize, 32-element blocks along last axis.
// R15 = FINAL: revert to R12, the session's best-measured kernel
// (74.5us kernel time, DRAM 82%, 6.50 TB/s = 81% of spec — at the B300
// LTS throughput cap for a 512MiB read+write stream).
//
// Winning invariant established over R2..R14:
//   * lane-contiguous warp memory ops (LDG.E.256, nL<=8/instr)
//   * 2 front-batched 256-bit loads per thread (16 lines in flight/warp)
//   * 32 regs (__launch_bounds__(512,4)) -> 100% theoretical occupancy
//   * many-short-CTA launch grid (8192x512): fresh CTAs front-batch loads
//     with no stores ahead in program order
//   * MX block spans 2 lanes -> single shfl.xor(1) per 32-float block
// Departures tested and rejected: ILP=8 (regs), strided ownership (nL),
// persistence x3 (MLP loss), zero-shuffle (nL=32), .cs on/off (neutral).
//
// All scales are exact powers of two built by bit manipulation, so every
// multiply matches the reference's fp32 divide bit-for-bit (rel_err 0.0
// on every round).

static constexpr int EMAX = 8;           // e4m3
static constexpr float MAX_NORM = 448.0f;

__device__ __forceinline__ void ldg256cs(const float* p, float* v) {
    asm volatile(
        "ld.global.cs.v8.f32 {%0,%1,%2,%3,%4,%5,%6,%7}, [%8];"
        : "=f"(v[0]), "=f"(v[1]), "=f"(v[2]), "=f"(v[3]),
          "=f"(v[4]), "=f"(v[5]), "=f"(v[6]), "=f"(v[7])
        : "l"(p));
}

__device__ __forceinline__ void stg256cs(float* p, const float* v) {
    asm volatile(
        "st.global.cs.v8.f32 [%0], {%1,%2,%3,%4,%5,%6,%7,%8};"
        :: "l"(p),
           "f"(v[0]), "f"(v[1]), "f"(v[2]), "f"(v[3]),
           "f"(v[4]), "f"(v[5]), "f"(v[6]), "f"(v[7])
        : "memory");
}

__device__ __forceinline__ float quant_e4m3(float x, float iscale, float scale) {
    float a = x * iscale;                          // exact (iscale = 2^k)
    uint32_t au = __float_as_uint(a);
    uint32_t ab = au & 0x7fffffffu;                // |a|
    int pe = (int)(ab >> 23) - 127;                // floor(log2|a|), exact for normals
    pe = max(pe, -6);                              // MIN_EXP (denorm region clamp)
    // lshift = 2^(3-pe), inv_lshift = 2^(pe-3); pe in [-6, 8] -> both normal
    float lsh  = __uint_as_float((uint32_t)(130 - pe) << 23);
    float ilsh = __uint_as_float((uint32_t)(124 + pe) << 23);
    // round-half-away-from-zero on magnitude: product is exact, +0.5 rounds once
    float r = floorf(__uint_as_float(ab) * lsh + 0.5f);
    float m = fminf(r * ilsh, MAX_NORM);           // saturate to e4m3 max normal
    float res = m * scale;
    return __uint_as_float(__float_as_uint(res) | (au & 0x80000000u));
}

__global__ void __launch_bounds__(512, 4) mxq_kernel(const float* __restrict__ in,
                                                     float* __restrict__ out) {
    int gid = blockIdx.x * blockDim.x + threadIdx.x;
    long base = (long)gid * 16;                    // 16 contiguous floats

    // Front-batched 256-bit loads (16 lines in flight per warp)
    float a[8], b[8];
    ldg256cs(in + base, a);
    ldg256cs(in + base + 8, b);

    // amax over this thread's 16, then one shfl across the 2-lane block group
    float m = fmaxf(fabsf(a[0]), fabsf(a[1]));
    m = fmaxf(m, fmaxf(fabsf(a[2]), fabsf(a[3])));
    m = fmaxf(m, fmaxf(fabsf(a[4]), fabsf(a[5])));
    m = fmaxf(m, fmaxf(fabsf(a[6]), fabsf(a[7])));
    m = fmaxf(m, fmaxf(fabsf(b[0]), fabsf(b[1])));
    m = fmaxf(m, fmaxf(fabsf(b[2]), fabsf(b[3])));
    m = fmaxf(m, fmaxf(fabsf(b[4]), fabsf(b[5])));
    m = fmaxf(m, fmaxf(fabsf(b[6]), fabsf(b[7])));
    m = fmaxf(m, __shfl_xor_sync(0xffffffffu, m, 1));

    int e = (int)(__float_as_uint(m) >> 23);       // m >= 0, no sign bit
    int se = e - 127 - EMAX;
    se = max(se, -127);
    float scale  = __uint_as_float((uint32_t)(se + 127) << 23);
    float iscale = __uint_as_float((uint32_t)(127 - se) << 23);

    // Process + store first half (registers retire early), then second half.
#pragma unroll
    for (int i = 0; i < 8; i++) a[i] = quant_e4m3(a[i], iscale, scale);
    stg256cs(out + base, a);
#pragma unroll
    for (int i = 0; i < 8; i++) b[i] = quant_e4m3(b[i], iscale, scale);
    stg256cs(out + base + 8, b);
}

extern "C" void kernel_launch(void* const* d_in, const int* in_sizes, int n_in,
                              void* d_out, int out_size) {
    const float* in = (const float*)d_in[0];
    float* out = (float*)d_out;
    int n = out_size;                              // 67,108,864 floats
    int threads = 512;
    int total_threads = n / 16;                    // 4,194,304
    int blocks = total_threads / threads;          // 8192
    mxq_kernel<<<blocks, threads>>>(in, out);
}